// round 3
// baseline (speedup 1.0000x reference)
#include <cuda_runtime.h>

// Problem constants (fixed by the reference)
#define B_    2
#define T_    512
#define D_    768
#define E_    256
#define P_    65536
#define H1_   768
#define H2_   384
#define NL_   5
#define ROWS_ (B_*E_)          // 512 fused (b,e) rows

// ---------------- scratch (static device globals; no allocation) ------------
__device__ float g_pooled[ROWS_*D_];       // mean-pooled spans        [512,768]
__device__ float g_eph[NL_*H1_];           // emb @ Wh1[768:]          [5,768]
__device__ float g_ept[NL_*H1_];           // emb @ Wt1[768:]          [5,768]
__device__ float g_h1h[ROWS_*H1_];         // head layer-1 out         [512,768]
__device__ float g_h1t[ROWS_*H1_];         // tail layer-1 out         [512,768]
__device__ float g_head[ROWS_*H2_];        // head_all                 [512,384]
__device__ float g_tail[ROWS_*H2_];        // tail_all                 [512,384]
__device__ float g_wblt[H2_*2*H2_];        // W_bil transposed: [i][o*384+j]
__device__ float g_u[ROWS_*2*H2_];         // head @ W_bil : [row][o*384+j]
__device__ float g_V[B_*2*E_*E_];          // dense biaffine table [b][o][hh][tt]
__device__ float g_lh[ROWS_*2];            // head @ W_lin[:384]
__device__ float g_lt[ROWS_*2];            // tail @ W_lin[384:]

// ---------------- 1) span mean-pooling --------------------------------------
__global__ void pool_kernel(const float* __restrict__ hs,
                            const int* __restrict__ st,
                            const int* __restrict__ en) {
    int be = blockIdx.x;             // 0..511
    int b  = be >> 8;
    int s  = st[be];
    int len = en[be] - s;
    int cl  = len < 1 ? 1 : len;
    float inv = 1.0f / (float)cl;
    const float* base = hs + ((size_t)(b*T_ + s))*D_;
    for (int d = threadIdx.x; d < D_; d += blockDim.x) {
        float acc = 0.f;
        for (int t = 0; t < len; t++) acc += base[(size_t)t*D_ + d];
        g_pooled[(size_t)be*D_ + d] = acc * inv;
    }
}

// ---------------- 2) per-label projection through W1[768:] ------------------
__global__ void labelproj_kernel(const float* __restrict__ emb,
                                 const float* __restrict__ W1,
                                 float* __restrict__ out) {
    int gid = blockIdx.x*blockDim.x + threadIdx.x;  // 5*768 = 3840
    if (gid >= NL_*H1_) return;
    int l = gid / H1_, n = gid - l*H1_;
    const float* wp = W1 + (size_t)D_*H1_ + n;      // rows 768..1535, col n
    const float* ep = emb + (size_t)l*D_;
    float acc = 0.f;
    #pragma unroll 4
    for (int k = 0; k < D_; k++) acc += ep[k] * wp[(size_t)k*H1_];
    out[gid] = acc;
}

// ---------------- generic NN SGEMM: C = act(A[M,K] @ W[K,N] + bias (+lbias)) -
// 64x64 block tile, BK=16, 256 threads, 4x4 register tile per thread.
// M%64==0, N%64==0, K%16==0 guaranteed by the shapes used here.
__global__ __launch_bounds__(256) void sgemm_nn(
    const float* __restrict__ A, const float* __restrict__ W,
    const float* __restrict__ bias, const int* __restrict__ labels,
    const float* __restrict__ lbias, float* __restrict__ C,
    int M, int N, int K, int relu)
{
    __shared__ float As[16][64];   // As[k][m]
    __shared__ float Bs[16][64];   // Bs[k][n]
    int tid = threadIdx.x;
    int bm = blockIdx.y * 64, bn = blockIdx.x * 64;
    int tx = tid & 15, ty = tid >> 4;

    int arow = tid >> 2, ac4 = (tid & 3) * 4;     // A tile: 64 rows x 16 cols
    int brow = tid >> 4, bc4 = (tid & 15) * 4;    // W tile: 16 rows x 64 cols
    const float* Ap = A + (size_t)(bm + arow)*K + ac4;
    const float* Wp = W + (size_t)brow*N + bn + bc4;

    float acc[4][4] = {};
    for (int k0 = 0; k0 < K; k0 += 16) {
        float4 av = *(const float4*)Ap;  Ap += 16;
        float4 wv = *(const float4*)Wp;  Wp += (size_t)16*N;
        As[ac4+0][arow] = av.x; As[ac4+1][arow] = av.y;
        As[ac4+2][arow] = av.z; As[ac4+3][arow] = av.w;
        *(float4*)&Bs[brow][bc4] = wv;
        __syncthreads();
        #pragma unroll
        for (int k = 0; k < 16; k++) {
            float4 a = *(const float4*)&As[k][ty*4];
            float4 b = *(const float4*)&Bs[k][tx*4];
            acc[0][0] += a.x*b.x; acc[0][1] += a.x*b.y; acc[0][2] += a.x*b.z; acc[0][3] += a.x*b.w;
            acc[1][0] += a.y*b.x; acc[1][1] += a.y*b.y; acc[1][2] += a.y*b.z; acc[1][3] += a.y*b.w;
            acc[2][0] += a.z*b.x; acc[2][1] += a.z*b.y; acc[2][2] += a.z*b.z; acc[2][3] += a.z*b.w;
            acc[3][0] += a.w*b.x; acc[3][1] += a.w*b.y; acc[3][2] += a.w*b.z; acc[3][3] += a.w*b.w;
        }
        __syncthreads();
    }

    int ncol = bn + tx*4;
    float bb[4] = {0.f,0.f,0.f,0.f};
    if (bias) { bb[0]=bias[ncol]; bb[1]=bias[ncol+1]; bb[2]=bias[ncol+2]; bb[3]=bias[ncol+3]; }
    #pragma unroll
    for (int i = 0; i < 4; i++) {
        int row = bm + ty*4 + i;
        float lb[4] = {0.f,0.f,0.f,0.f};
        if (lbias) {
            const float* lp = lbias + (size_t)labels[row]*N + ncol;
            lb[0]=lp[0]; lb[1]=lp[1]; lb[2]=lp[2]; lb[3]=lp[3];
        }
        float4 v;
        v.x = acc[i][0] + bb[0] + lb[0];
        v.y = acc[i][1] + bb[1] + lb[1];
        v.z = acc[i][2] + bb[2] + lb[2];
        v.w = acc[i][3] + bb[3] + lb[3];
        if (relu) {
            v.x = fmaxf(v.x, 0.f); v.y = fmaxf(v.y, 0.f);
            v.z = fmaxf(v.z, 0.f); v.w = fmaxf(v.w, 0.f);
        }
        *(float4*)(C + (size_t)row*N + ncol) = v;
    }
}

// ---------------- W_bil transpose: [o][i][j] -> [i][o*384+j] ----------------
__global__ void wbl_transpose(const float* __restrict__ Wbil) {
    int gid = blockIdx.x*blockDim.x + threadIdx.x;   // 2*384*384
    if (gid >= 2*H2_*H2_) return;
    int o = gid / (H2_*H2_);
    int r = gid - o*(H2_*H2_);
    int i = r / H2_, j = r - i*H2_;
    g_wblt[(size_t)i*(2*H2_) + o*H2_ + j] = Wbil[gid];
}

// ---------------- dense biaffine table: V[b][o] = U_bo @ tail_b^T -----------
// M=N=256, K=384.  A = g_u (lda=768, col offset o*384), B = g_tail (ldb=384).
__global__ __launch_bounds__(256) void sgemm_nt_V() {
    __shared__ float As[16][64];
    __shared__ float Bs[16][64];
    int bo = blockIdx.z;            // b*2+o
    int b = bo >> 1, o = bo & 1;
    const float* A  = g_u    + (size_t)b*E_*(2*H2_) + o*H2_;  // lda = 768
    const float* Bm = g_tail + (size_t)b*E_*H2_;              // ldb = 384
    float* C = g_V + (size_t)bo*E_*E_;                        // ldc = 256

    int tid = threadIdx.x;
    int bm = blockIdx.y * 64, bn = blockIdx.x * 64;
    int tx = tid & 15, ty = tid >> 4;
    int lr = tid >> 2, lc4 = (tid & 3) * 4;
    const float* Ap = A  + (size_t)(bm + lr)*(2*H2_) + lc4;
    const float* Bp = Bm + (size_t)(bn + lr)*H2_ + lc4;

    float acc[4][4] = {};
    for (int k0 = 0; k0 < H2_; k0 += 16) {
        float4 av = *(const float4*)Ap;  Ap += 16;
        float4 bv = *(const float4*)Bp;  Bp += 16;
        As[lc4+0][lr] = av.x; As[lc4+1][lr] = av.y;
        As[lc4+2][lr] = av.z; As[lc4+3][lr] = av.w;
        Bs[lc4+0][lr] = bv.x; Bs[lc4+1][lr] = bv.y;
        Bs[lc4+2][lr] = bv.z; Bs[lc4+3][lr] = bv.w;
        __syncthreads();
        #pragma unroll
        for (int k = 0; k < 16; k++) {
            float4 a = *(const float4*)&As[k][ty*4];
            float4 bb = *(const float4*)&Bs[k][tx*4];
            acc[0][0] += a.x*bb.x; acc[0][1] += a.x*bb.y; acc[0][2] += a.x*bb.z; acc[0][3] += a.x*bb.w;
            acc[1][0] += a.y*bb.x; acc[1][1] += a.y*bb.y; acc[1][2] += a.y*bb.z; acc[1][3] += a.y*bb.w;
            acc[2][0] += a.z*bb.x; acc[2][1] += a.z*bb.y; acc[2][2] += a.z*bb.z; acc[2][3] += a.z*bb.w;
            acc[3][0] += a.w*bb.x; acc[3][1] += a.w*bb.y; acc[3][2] += a.w*bb.z; acc[3][3] += a.w*bb.w;
        }
        __syncthreads();
    }
    #pragma unroll
    for (int i = 0; i < 4; i++) {
        float4 v = make_float4(acc[i][0], acc[i][1], acc[i][2], acc[i][3]);
        *(float4*)(C + (size_t)(bm + ty*4 + i)*E_ + bn + tx*4) = v;
    }
}

// ---------------- per-entity linear terms lh/lt -----------------------------
__global__ void lhlt_kernel(const float* __restrict__ Wlin) {
    int gid  = blockIdx.x*blockDim.x + threadIdx.x;
    int w    = gid >> 5;            // entity row 0..511
    int lane = gid & 31;
    if (w >= ROWS_) return;
    float s0=0.f, s1=0.f, s2=0.f, s3=0.f;
    for (int j = lane; j < H2_; j += 32) {
        float hv = g_head[(size_t)w*H2_ + j];
        float tv = g_tail[(size_t)w*H2_ + j];
        s0 += hv * Wlin[j*2+0];
        s1 += hv * Wlin[j*2+1];
        s2 += tv * Wlin[(H2_+j)*2+0];
        s3 += tv * Wlin[(H2_+j)*2+1];
    }
    #pragma unroll
    for (int off = 16; off > 0; off >>= 1) {
        s0 += __shfl_down_sync(0xffffffffu, s0, off);
        s1 += __shfl_down_sync(0xffffffffu, s1, off);
        s2 += __shfl_down_sync(0xffffffffu, s2, off);
        s3 += __shfl_down_sync(0xffffffffu, s3, off);
    }
    if (lane == 0) {
        g_lh[w*2+0] = s0; g_lh[w*2+1] = s1;
        g_lt[w*2+0] = s2; g_lt[w*2+1] = s3;
    }
}

// ---------------- final per-pair lookup + assembly --------------------------
__global__ void gather_kernel(const int* __restrict__ hidx,
                              const int* __restrict__ tidx,
                              const float* __restrict__ blin,
                              float* __restrict__ out) {
    int gid = blockIdx.x*blockDim.x + threadIdx.x;   // B*P = 131072
    if (gid >= B_*P_) return;
    int b = gid >> 16;
    int h = hidx[gid];
    int t = tidx[gid];
    int rh = (b << 8) + h;
    int rt = (b << 8) + t;
    float v0 = g_V[((size_t)(b*2+0) << 16) + (h << 8) + t];
    float v1 = g_V[((size_t)(b*2+1) << 16) + (h << 8) + t];
    float2 r;
    r.x = v0 + g_lh[rh*2+0] + g_lt[rt*2+0] + blin[0];
    r.y = v1 + g_lh[rh*2+1] + g_lt[rt*2+1] + blin[1];
    ((float2*)out)[gid] = r;
}

// ---------------- launch ----------------------------------------------------
extern "C" void kernel_launch(void* const* d_in, const int* in_sizes, int n_in,
                              void* d_out, int out_size) {
    const float* hs   = (const float*)d_in[0];
    const float* emb  = (const float*)d_in[1];
    const float* Wh1  = (const float*)d_in[2];
    const float* bh1  = (const float*)d_in[3];
    const float* Wh2  = (const float*)d_in[4];
    const float* bh2  = (const float*)d_in[5];
    const float* Wt1  = (const float*)d_in[6];
    const float* bt1  = (const float*)d_in[7];
    const float* Wt2  = (const float*)d_in[8];
    const float* bt2  = (const float*)d_in[9];
    const float* Wbil = (const float*)d_in[10];
    const float* Wlin = (const float*)d_in[11];
    const float* blin = (const float*)d_in[12];
    const int*   est  = (const int*)d_in[13];
    const int*   een  = (const int*)d_in[14];
    const int*   elab = (const int*)d_in[15];
    const int*   hidx = (const int*)d_in[16];
    const int*   tidx = (const int*)d_in[17];

    float *p_pooled, *p_eph, *p_ept, *p_h1h, *p_h1t, *p_head, *p_tail, *p_wblt, *p_u;
    cudaGetSymbolAddress((void**)&p_pooled, g_pooled);
    cudaGetSymbolAddress((void**)&p_eph,    g_eph);
    cudaGetSymbolAddress((void**)&p_ept,    g_ept);
    cudaGetSymbolAddress((void**)&p_h1h,    g_h1h);
    cudaGetSymbolAddress((void**)&p_h1t,    g_h1t);
    cudaGetSymbolAddress((void**)&p_head,   g_head);
    cudaGetSymbolAddress((void**)&p_tail,   g_tail);
    cudaGetSymbolAddress((void**)&p_wblt,   g_wblt);
    cudaGetSymbolAddress((void**)&p_u,      g_u);

    // 1) span mean pooling -> g_pooled [512,768]
    pool_kernel<<<ROWS_, 256>>>(hs, est, een);

    // 2) label projections (emb @ W1[768:]) for head & tail nets
    labelproj_kernel<<<(NL_*H1_ + 255)/256, 256>>>(emb, Wh1, p_eph);
    labelproj_kernel<<<(NL_*H1_ + 255)/256, 256>>>(emb, Wt1, p_ept);

    // 2b) W_bil transpose (independent, overlapped in-order is fine)
    wbl_transpose<<<(2*H2_*H2_ + 255)/256, 256>>>(Wbil);

    // 3) FFNN layer 1: relu(pooled @ W1[:768] + b1 + eph[label])  K=768
    sgemm_nn<<<dim3(H1_/64, ROWS_/64), 256>>>(p_pooled, Wh1, bh1, elab, p_eph,
                                              p_h1h, ROWS_, H1_, D_, 1);
    sgemm_nn<<<dim3(H1_/64, ROWS_/64), 256>>>(p_pooled, Wt1, bt1, elab, p_ept,
                                              p_h1t, ROWS_, H1_, D_, 1);

    // 4) FFNN layer 2: relu(h1 @ W2 + b2)  [512,768]->[512,384]
    sgemm_nn<<<dim3(H2_/64, ROWS_/64), 256>>>(p_h1h, Wh2, bh2, nullptr, nullptr,
                                              p_head, ROWS_, H2_, H1_, 1);
    sgemm_nn<<<dim3(H2_/64, ROWS_/64), 256>>>(p_h1t, Wt2, bt2, nullptr, nullptr,
                                              p_tail, ROWS_, H2_, H1_, 1);

    // 5) u = head @ W_bil^T-layout : [512,384] @ [384,768] -> [512,768]
    sgemm_nn<<<dim3((2*H2_)/64, ROWS_/64), 256>>>(p_head, p_wblt, nullptr, nullptr,
                                                  nullptr, p_u, ROWS_, 2*H2_, H2_, 0);

    // 6) per-entity linear terms
    lhlt_kernel<<<(ROWS_*32 + 255)/256, 256>>>(Wlin);

    // 7) dense biaffine table V[b,o] = U_bo @ tail_b^T  (256x256x384, 4 batches)
    sgemm_nt_V<<<dim3(E_/64, E_/64, B_*2), 256>>>();

    // 8) per-pair lookup + linear terms + bias
    gather_kernel<<<(B_*P_ + 255)/256, 256>>>(hidx, tidx, blin, (float*)d_out);
}

// round 4
// speedup vs baseline: 1.7761x; 1.7761x over previous
#include <cuda_runtime.h>

// Problem constants (fixed by the reference)
#define B_    2
#define T_    512
#define D_    768
#define E_    256
#define P_    65536
#define H1_   768
#define H2_   384
#define NL_   5
#define ROWS_ (B_*E_)          // 512 fused (b,e) rows

// ---------------- scratch (static device globals; no allocation) ------------
__device__ float g_pooled[ROWS_*D_];       // mean-pooled spans        [512,768]
__device__ float g_eph[NL_*H1_];           // emb @ Wh1[768:]          [5,768]
__device__ float g_ept[NL_*H1_];           // emb @ Wt1[768:]          [5,768]
__device__ float g_h1h[ROWS_*H1_];         // head layer-1 out         [512,768]
__device__ float g_h1t[ROWS_*H1_];         // tail layer-1 out         [512,768]
__device__ float g_head[ROWS_*H2_];        // head_all                 [512,384]
__device__ float g_tail[ROWS_*H2_];        // tail_all                 [512,384]
__device__ float g_u[ROWS_*2*H2_];         // head @ W_bil : [row][o*384+j]
__device__ float g_V[B_*2*E_*E_];          // dense biaffine table [b][o][hh][tt]
__device__ float g_lh[ROWS_*2];            // head @ W_lin[:384]
__device__ float g_lt[ROWS_*2];            // tail @ W_lin[384:]

// ---------------- 1) span mean-pooling --------------------------------------
__global__ void pool_kernel(const float* __restrict__ hs,
                            const int* __restrict__ st,
                            const int* __restrict__ en) {
    int be = blockIdx.x;             // 0..511
    int b  = be >> 8;
    int s  = st[be];
    int len = en[be] - s;
    int cl  = len < 1 ? 1 : len;
    float inv = 1.0f / (float)cl;
    const float* base = hs + ((size_t)(b*T_ + s))*D_;
    for (int d = threadIdx.x; d < D_; d += blockDim.x) {
        float acc = 0.f;
        for (int t = 0; t < len; t++) acc += base[(size_t)t*D_ + d];
        g_pooled[(size_t)be*D_ + d] = acc * inv;
    }
}

// ---------------- 2) per-label projection through W1[768:] for BOTH nets ----
__global__ void labelproj2_kernel(const float* __restrict__ emb,
                                  const float* __restrict__ Wh1,
                                  const float* __restrict__ Wt1) {
    int gid = blockIdx.x*blockDim.x + threadIdx.x;  // 2*5*768 = 7680
    if (gid >= 2*NL_*H1_) return;
    int half = gid / (NL_*H1_);
    int r    = gid - half*(NL_*H1_);
    int l = r / H1_, n = r - l*H1_;
    const float* W1 = half ? Wt1 : Wh1;
    const float* wp = W1 + (size_t)D_*H1_ + n;      // rows 768..1535, col n
    const float* ep = emb + (size_t)l*D_;
    float acc = 0.f;
    #pragma unroll 4
    for (int k = 0; k < D_; k++) acc += ep[k] * wp[(size_t)k*H1_];
    if (half) g_ept[r] = acc; else g_eph[r] = acc;
}

// ---------------- double-buffered NN SGEMM ----------------------------------
// C[z] = act(A[z][M,K] @ W[z][K,N] + bias[z] (+ lbias[z][label[row]]))
// 64x64 block tile, BK=16, 256 threads, 4x4 register tile, 2 smem buffers,
// ONE __syncthreads per k-iteration. Segmented-B: element B[k][n] lives at
// W + (n/segw)*segstride + k*ldb + (n%segw).  For plain GEMMs segw=N,
// segstride=0, ldb=N.  M%64==0, N%64==0 (and segw%64==0), K%16==0.
__global__ __launch_bounds__(256, 2) void sgemm_dbuf(
    const float* __restrict__ A0, const float* __restrict__ A1,
    const float* __restrict__ W0, const float* __restrict__ W1,
    const float* __restrict__ bias0, const float* __restrict__ bias1,
    const int* __restrict__ labels,
    const float* __restrict__ lb0, const float* __restrict__ lb1,
    float* __restrict__ C0, float* __restrict__ C1,
    int N, int K, int ldb, int segw, int segstride, int relu)
{
    __shared__ float As[2][16][64];   // As[buf][k][m]
    __shared__ float Bs[2][16][64];   // Bs[buf][k][n]

    int z = blockIdx.z;
    const float* A    = z ? A1 : A0;
    const float* W    = z ? W1 : W0;
    const float* bias = z ? bias1 : bias0;
    const float* lb   = z ? lb1 : lb0;
    float*       C    = z ? C1 : C0;

    int tid = threadIdx.x;
    int bm = blockIdx.y * 64, bn = blockIdx.x * 64;
    int tx = tid & 15, ty = tid >> 4;

    int arow = tid >> 2, ac4 = (tid & 3) * 4;     // A tile: 64 rows x 16 cols
    int brow = tid >> 4, bc4 = (tid & 15) * 4;    // W tile: 16 rows x 64 cols

    int seg = bn / segw;
    const float* Ap = A + (size_t)(bm + arow)*K + ac4;
    const float* Wp = W + (size_t)seg*segstride + (bn - seg*segw)
                        + (size_t)brow*ldb + bc4;

    // prologue: load k-tile 0 into buffer 0
    float4 av = *(const float4*)Ap;
    float4 wv = *(const float4*)Wp;
    As[0][ac4+0][arow] = av.x; As[0][ac4+1][arow] = av.y;
    As[0][ac4+2][arow] = av.z; As[0][ac4+3][arow] = av.w;
    *(float4*)&Bs[0][brow][bc4] = wv;
    __syncthreads();

    float acc[4][4] = {};
    int nk = K >> 4;
    for (int t = 0; t < nk; t++) {
        int cur = t & 1, nxt = cur ^ 1;
        if (t + 1 < nk) {                 // prefetch next k-tile into registers
            av = *(const float4*)(Ap + (t+1)*16);
            wv = *(const float4*)(Wp + (size_t)(t+1)*16*ldb);
        }
        #pragma unroll
        for (int k = 0; k < 16; k++) {
            float4 a = *(const float4*)&As[cur][k][ty*4];
            float4 b = *(const float4*)&Bs[cur][k][tx*4];
            acc[0][0] += a.x*b.x; acc[0][1] += a.x*b.y; acc[0][2] += a.x*b.z; acc[0][3] += a.x*b.w;
            acc[1][0] += a.y*b.x; acc[1][1] += a.y*b.y; acc[1][2] += a.y*b.z; acc[1][3] += a.y*b.w;
            acc[2][0] += a.z*b.x; acc[2][1] += a.z*b.y; acc[2][2] += a.z*b.z; acc[2][3] += a.z*b.w;
            acc[3][0] += a.w*b.x; acc[3][1] += a.w*b.y; acc[3][2] += a.w*b.z; acc[3][3] += a.w*b.w;
        }
        if (t + 1 < nk) {
            As[nxt][ac4+0][arow] = av.x; As[nxt][ac4+1][arow] = av.y;
            As[nxt][ac4+2][arow] = av.z; As[nxt][ac4+3][arow] = av.w;
            *(float4*)&Bs[nxt][brow][bc4] = wv;
        }
        __syncthreads();
    }

    int ncol = bn + tx*4;
    float bb[4] = {0.f,0.f,0.f,0.f};
    if (bias) { bb[0]=bias[ncol]; bb[1]=bias[ncol+1]; bb[2]=bias[ncol+2]; bb[3]=bias[ncol+3]; }
    #pragma unroll
    for (int i = 0; i < 4; i++) {
        int row = bm + ty*4 + i;
        float lv[4] = {0.f,0.f,0.f,0.f};
        if (lb) {
            const float* lp = lb + (size_t)labels[row]*N + ncol;
            lv[0]=lp[0]; lv[1]=lp[1]; lv[2]=lp[2]; lv[3]=lp[3];
        }
        float4 v;
        v.x = acc[i][0] + bb[0] + lv[0];
        v.y = acc[i][1] + bb[1] + lv[1];
        v.z = acc[i][2] + bb[2] + lv[2];
        v.w = acc[i][3] + bb[3] + lv[3];
        if (relu) {
            v.x = fmaxf(v.x, 0.f); v.y = fmaxf(v.y, 0.f);
            v.z = fmaxf(v.z, 0.f); v.w = fmaxf(v.w, 0.f);
        }
        *(float4*)(C + (size_t)row*N + ncol) = v;
    }
}

// ---------------- dense biaffine table: V[b][o] = U_bo @ tail_b^T -----------
// M=N=256, K=384.  A = g_u (lda=768, col offset o*384), B = g_tail (ldb=384).
// Same 64x64x16 double-buffered scheme (both operands K-contiguous -> NT).
__global__ __launch_bounds__(256, 2) void sgemm_nt_V() {
    __shared__ float As[2][16][64];
    __shared__ float Bs[2][16][64];
    int bo = blockIdx.z;            // b*2+o
    int b = bo >> 1, o = bo & 1;
    const float* A  = g_u    + (size_t)b*E_*(2*H2_) + o*H2_;  // lda = 768
    const float* Bm = g_tail + (size_t)b*E_*H2_;              // ldb = 384
    float* C = g_V + (size_t)bo*E_*E_;                        // ldc = 256

    int tid = threadIdx.x;
    int bm = blockIdx.y * 64, bn = blockIdx.x * 64;
    int tx = tid & 15, ty = tid >> 4;
    int lr = tid >> 2, lc4 = (tid & 3) * 4;
    const float* Ap = A  + (size_t)(bm + lr)*(2*H2_) + lc4;
    const float* Bp = Bm + (size_t)(bn + lr)*H2_ + lc4;

    float4 av = *(const float4*)Ap;
    float4 bv = *(const float4*)Bp;
    As[0][lc4+0][lr] = av.x; As[0][lc4+1][lr] = av.y;
    As[0][lc4+2][lr] = av.z; As[0][lc4+3][lr] = av.w;
    Bs[0][lc4+0][lr] = bv.x; Bs[0][lc4+1][lr] = bv.y;
    Bs[0][lc4+2][lr] = bv.z; Bs[0][lc4+3][lr] = bv.w;
    __syncthreads();

    float acc[4][4] = {};
    const int nk = H2_ >> 4;   // 24
    for (int t = 0; t < nk; t++) {
        int cur = t & 1, nxt = cur ^ 1;
        if (t + 1 < nk) {
            av = *(const float4*)(Ap + (t+1)*16);
            bv = *(const float4*)(Bp + (t+1)*16);
        }
        #pragma unroll
        for (int k = 0; k < 16; k++) {
            float4 a  = *(const float4*)&As[cur][k][ty*4];
            float4 bb = *(const float4*)&Bs[cur][k][tx*4];
            acc[0][0] += a.x*bb.x; acc[0][1] += a.x*bb.y; acc[0][2] += a.x*bb.z; acc[0][3] += a.x*bb.w;
            acc[1][0] += a.y*bb.x; acc[1][1] += a.y*bb.y; acc[1][2] += a.y*bb.z; acc[1][3] += a.y*bb.w;
            acc[2][0] += a.z*bb.x; acc[2][1] += a.z*bb.y; acc[2][2] += a.z*bb.z; acc[2][3] += a.z*bb.w;
            acc[3][0] += a.w*bb.x; acc[3][1] += a.w*bb.y; acc[3][2] += a.w*bb.z; acc[3][3] += a.w*bb.w;
        }
        if (t + 1 < nk) {
            As[nxt][lc4+0][lr] = av.x; As[nxt][lc4+1][lr] = av.y;
            As[nxt][lc4+2][lr] = av.z; As[nxt][lc4+3][lr] = av.w;
            Bs[nxt][lc4+0][lr] = bv.x; Bs[nxt][lc4+1][lr] = bv.y;
            Bs[nxt][lc4+2][lr] = bv.z; Bs[nxt][lc4+3][lr] = bv.w;
        }
        __syncthreads();
    }
    #pragma unroll
    for (int i = 0; i < 4; i++) {
        float4 v = make_float4(acc[i][0], acc[i][1], acc[i][2], acc[i][3]);
        *(float4*)(C + (size_t)(bm + ty*4 + i)*E_ + bn + tx*4) = v;
    }
}

// ---------------- per-entity linear terms lh/lt -----------------------------
__global__ void lhlt_kernel(const float* __restrict__ Wlin) {
    int gid  = blockIdx.x*blockDim.x + threadIdx.x;
    int w    = gid >> 5;            // entity row 0..511
    int lane = gid & 31;
    if (w >= ROWS_) return;
    float s0=0.f, s1=0.f, s2=0.f, s3=0.f;
    for (int j = lane; j < H2_; j += 32) {
        float hv = g_head[(size_t)w*H2_ + j];
        float tv = g_tail[(size_t)w*H2_ + j];
        s0 += hv * Wlin[j*2+0];
        s1 += hv * Wlin[j*2+1];
        s2 += tv * Wlin[(H2_+j)*2+0];
        s3 += tv * Wlin[(H2_+j)*2+1];
    }
    #pragma unroll
    for (int off = 16; off > 0; off >>= 1) {
        s0 += __shfl_down_sync(0xffffffffu, s0, off);
        s1 += __shfl_down_sync(0xffffffffu, s1, off);
        s2 += __shfl_down_sync(0xffffffffu, s2, off);
        s3 += __shfl_down_sync(0xffffffffu, s3, off);
    }
    if (lane == 0) {
        g_lh[w*2+0] = s0; g_lh[w*2+1] = s1;
        g_lt[w*2+0] = s2; g_lt[w*2+1] = s3;
    }
}

// ---------------- final per-pair lookup + assembly --------------------------
__global__ void gather_kernel(const int* __restrict__ hidx,
                              const int* __restrict__ tidx,
                              const float* __restrict__ blin,
                              float* __restrict__ out) {
    int gid = blockIdx.x*blockDim.x + threadIdx.x;   // B*P = 131072
    if (gid >= B_*P_) return;
    int b = gid >> 16;
    int h = hidx[gid];
    int t = tidx[gid];
    int rh = (b << 8) + h;
    int rt = (b << 8) + t;
    float v0 = g_V[((size_t)(b*2+0) << 16) + (h << 8) + t];
    float v1 = g_V[((size_t)(b*2+1) << 16) + (h << 8) + t];
    float2 r;
    r.x = v0 + g_lh[rh*2+0] + g_lt[rt*2+0] + blin[0];
    r.y = v1 + g_lh[rh*2+1] + g_lt[rt*2+1] + blin[1];
    ((float2*)out)[gid] = r;
}

// ---------------- launch ----------------------------------------------------
extern "C" void kernel_launch(void* const* d_in, const int* in_sizes, int n_in,
                              void* d_out, int out_size) {
    const float* hs   = (const float*)d_in[0];
    const float* emb  = (const float*)d_in[1];
    const float* Wh1  = (const float*)d_in[2];
    const float* bh1  = (const float*)d_in[3];
    const float* Wh2  = (const float*)d_in[4];
    const float* bh2  = (const float*)d_in[5];
    const float* Wt1  = (const float*)d_in[6];
    const float* bt1  = (const float*)d_in[7];
    const float* Wt2  = (const float*)d_in[8];
    const float* bt2  = (const float*)d_in[9];
    const float* Wbil = (const float*)d_in[10];
    const float* Wlin = (const float*)d_in[11];
    const float* blin = (const float*)d_in[12];
    const int*   est  = (const int*)d_in[13];
    const int*   een  = (const int*)d_in[14];
    const int*   elab = (const int*)d_in[15];
    const int*   hidx = (const int*)d_in[16];
    const int*   tidx = (const int*)d_in[17];

    float *p_pooled, *p_eph, *p_ept, *p_h1h, *p_h1t, *p_head, *p_tail, *p_u;
    cudaGetSymbolAddress((void**)&p_pooled, g_pooled);
    cudaGetSymbolAddress((void**)&p_eph,    g_eph);
    cudaGetSymbolAddress((void**)&p_ept,    g_ept);
    cudaGetSymbolAddress((void**)&p_h1h,    g_h1h);
    cudaGetSymbolAddress((void**)&p_h1t,    g_h1t);
    cudaGetSymbolAddress((void**)&p_head,   g_head);
    cudaGetSymbolAddress((void**)&p_tail,   g_tail);
    cudaGetSymbolAddress((void**)&p_u,      g_u);

    // 1) span mean pooling -> g_pooled [512,768]
    pool_kernel<<<ROWS_, 256>>>(hs, est, een);

    // 2) label projections for BOTH nets in one launch
    labelproj2_kernel<<<(2*NL_*H1_ + 255)/256, 256>>>(emb, Wh1, Wt1);

    // 3) FFNN layer 1 (head+tail batched, z=2):
    //    relu(pooled @ W1[:768] + b1 + e{ph,pt}[label])   K=768, N=768
    sgemm_dbuf<<<dim3(H1_/64, ROWS_/64, 2), 256>>>(
        p_pooled, p_pooled, Wh1, Wt1, bh1, bt1, elab, p_eph, p_ept,
        p_h1h, p_h1t, H1_, D_, H1_, H1_, 0, 1);

    // 4) FFNN layer 2 (head+tail batched, z=2): relu(h1 @ W2 + b2)  K=768, N=384
    sgemm_dbuf<<<dim3(H2_/64, ROWS_/64, 2), 256>>>(
        p_h1h, p_h1t, Wh2, Wt2, bh2, bt2, nullptr, nullptr, nullptr,
        p_head, p_tail, H2_, H1_, H2_, H2_, 0, 1);

    // 5) per-entity linear terms (independent of u/V, only needs head/tail)
    lhlt_kernel<<<(ROWS_*32 + 255)/256, 256>>>(Wlin);

    // 6) u = head @ W_bil (direct, segmented-B: seg width 384, seg stride 384*384)
    sgemm_dbuf<<<dim3((2*H2_)/64, ROWS_/64, 1), 256>>>(
        p_head, p_head, Wbil, Wbil, nullptr, nullptr, nullptr, nullptr, nullptr,
        p_u, p_u, 2*H2_, H2_, H2_, H2_, H2_*H2_, 0);

    // 7) dense biaffine table V[b,o] = U_bo @ tail_b^T  (256x256x384, 4 batches)
    sgemm_nt_V<<<dim3(E_/64, E_/64, B_*2), 256>>>();

    // 8) per-pair lookup + linear terms + bias
    gather_kernel<<<(B_*P_ + 255)/256, 256>>>(hidx, tidx, blin, (float*)d_out);
}